// round 7
// baseline (speedup 1.0000x reference)
#include <cuda_runtime.h>
#include <math.h>

#define BB 8
#define LL 16
#define T_TAB 65536
#define RMAX 256
#define N_PIX (RMAX * RMAX)
#define NCELLS 211538

__constant__ int c_res[LL] = {16, 19, 23, 28, 34, 40, 49, 58,
                              70, 84, 102, 122, 147, 177, 213, 256};
__constant__ int c_off[LL] = {0, 256, 617, 1146, 1930, 3086, 4686, 7087,
                              10451, 15351, 22407, 32811, 47695, 69304, 100633, 146002};

// Dense (de-hashed) grids.
__device__ float2 g_dense[BB][NCELLS];

// Effective weights. W0p/W1p TRANSPOSED: g_Wp[b][i][j] = Weff[j][i].
__device__ float g_W0p[BB][32][32];
__device__ float g_W1p[BB][32][32];
__device__ float g_W2[BB][3][32];

// ---------------------------------------------------------------------------
// f32x2 helpers
// ---------------------------------------------------------------------------
__device__ __forceinline__ unsigned long long pk2(float lo, float hi) {
    unsigned long long r;
    asm("mov.b64 %0, {%1, %2};" : "=l"(r) : "f"(lo), "f"(hi));
    return r;
}
__device__ __forceinline__ void upk2(unsigned long long v, float& lo, float& hi) {
    asm("mov.b64 {%0, %1}, %2;" : "=f"(lo), "=f"(hi) : "l"(v));
}
__device__ __forceinline__ unsigned long long fma2(unsigned long long a,
                                                   unsigned long long b,
                                                   unsigned long long c) {
    unsigned long long d;
    asm("fma.rn.f32x2 %0, %1, %2, %3;" : "=l"(d) : "l"(a), "l"(b), "l"(c));
    return d;
}

// ---------------------------------------------------------------------------
// Style projection + weight modulation, one block per batch (1024 threads).
// ---------------------------------------------------------------------------
__global__ void __launch_bounds__(1024)
modweights_kernel(const float* __restrict__ s,
                  const float* __restrict__ w0, const float* __restrict__ aw0, const float* __restrict__ ab0,
                  const float* __restrict__ w1, const float* __restrict__ aw1, const float* __restrict__ ab1,
                  const float* __restrict__ w2, const float* __restrict__ aw2, const float* __restrict__ ab2)
{
    const int b = blockIdx.x;
    const int wid = threadIdx.x >> 5, lane = threadIdx.x & 31;
    __shared__ float st[96];

    const float4* sv4 = (const float4*)(s + b * 512);
    for (int o = wid; o < 96; o += 32) {
        const int layer = o >> 5, i = o & 31;
        const float* aw = (layer == 0) ? aw0 : (layer == 1) ? aw1 : aw2;
        const float* ab = (layer == 0) ? ab0 : (layer == 1) ? ab1 : ab2;
        const float4* rw4 = (const float4*)(aw + i * 512);
        float acc = 0.f;
        #pragma unroll
        for (int it = 0; it < 4; it++) {
            float4 a = __ldg(sv4 + it * 32 + lane);
            float4 w = __ldg(rw4 + it * 32 + lane);
            acc += a.x * w.x + a.y * w.y + a.z * w.z + a.w * w.w;
        }
        #pragma unroll
        for (int d = 16; d > 0; d >>= 1) acc += __shfl_xor_sync(0xFFFFFFFFu, acc, d);
        if (lane == 0) st[o] = acc + __ldg(ab + i);
    }
    __syncthreads();

    const int tid = threadIdx.x;
    if (tid < 32) {
        const int j = tid;
        float wm[32]; float ss = 0.f;
        #pragma unroll
        for (int i = 0; i < 32; i++) { float v = w0[j * 32 + i] * st[i]; wm[i] = v; ss += v * v; }
        float d = rsqrtf(ss + 1e-8f);
        #pragma unroll
        for (int i = 0; i < 32; i++) g_W0p[b][i][j] = wm[i] * d;
    } else if (tid < 64) {
        const int j = tid - 32;
        float wm[32]; float ss = 0.f;
        #pragma unroll
        for (int i = 0; i < 32; i++) { float v = w1[j * 32 + i] * st[32 + i]; wm[i] = v; ss += v * v; }
        float d = rsqrtf(ss + 1e-8f);
        #pragma unroll
        for (int i = 0; i < 32; i++) g_W1p[b][i][j] = wm[i] * d;
    } else if (tid < 67) {
        const int j = tid - 64;
        float wm[32]; float ss = 0.f;
        #pragma unroll
        for (int i = 0; i < 32; i++) { float v = w2[j * 32 + i] * st[64 + i]; wm[i] = v; ss += v * v; }
        float d = rsqrtf(ss + 1e-8f);
        #pragma unroll
        for (int i = 0; i < 32; i++) g_W2[b][j][i] = wm[i] * d;
    }
}

// ---------------------------------------------------------------------------
// De-hash tables into dense per-level grids.
// ---------------------------------------------------------------------------
__global__ void __launch_bounds__(256)
densify_kernel(const float* __restrict__ tables)
{
    const int c = blockIdx.x * 256 + threadIdx.x;
    const int b = blockIdx.y;
    if (c >= NCELLS) return;
    int l = 0;
    #pragma unroll
    for (int k = 1; k < LL; k++) l += (c >= c_off[k]);
    const int local = c - c_off[l];
    const int r = c_res[l];
    const int y = local / r;
    const int x = local - y * r;
    const unsigned idx = ((unsigned)x ^ ((unsigned)y * 2654435761u)) & 65535u;
    const float2* tab = (const float2*)tables + ((size_t)b * LL + l) * T_TAB;
    g_dense[b][c] = __ldg(tab + idx);
}

// ---------------------------------------------------------------------------
// Fused: dense bilinear encode + MLP (f32x2), 1 pixel/thread, 32x8 tiles,
// software-pipelined level loop (prefetch next level's 4 gathers during
// current level's interp+GEMM). Progressive inter-layer consumption.
// launch_bounds(256, 2): 128-reg cap, demand ~110 -> no spill, 16 warps/SM.
// ---------------------------------------------------------------------------
__global__ void __launch_bounds__(256, 2)
fused_kernel(const float* __restrict__ b0, const float* __restrict__ b1,
             const float* __restrict__ b2, float* __restrict__ out)
{
    __shared__ __align__(16) float sW0p[32][32];
    __shared__ __align__(16) float sW1p[32][32];
    __shared__ __align__(16) float sW2[3][32];
    __shared__ float sb0[32], sb1[32], sb2[3];

    const int b = blockIdx.y;
    const int tid = threadIdx.x;

    for (int k = tid; k < 1024; k += 256) {
        ((float*)sW0p)[k] = ((const float*)g_W0p[b])[k];
        ((float*)sW1p)[k] = ((const float*)g_W1p[b])[k];
    }
    if (tid < 96) ((float*)sW2)[tid] = ((const float*)g_W2[b])[tid];
    if (tid < 32) { sb0[tid] = b0[tid]; sb1[tid] = b1[tid]; }
    if (tid < 3)  sb2[tid] = b2[tid];
    __syncthreads();

    // 32x8 tiles: 8 across, 32 down; warp = one 32-pixel row (coalesced).
    const int tile = blockIdx.x;                  // 0..255
    const int px = ((tile & 7) << 5) + (tid & 31);
    const int py = ((tile >> 3) << 3) + (tid >> 5);
    const float cx = (px + 0.5f) * (1.0f / RMAX);
    const float cy = (py + 0.5f) * (1.0f / RMAX);

    const unsigned long long* dense = (const unsigned long long*)g_dense[b];

    // Layer 0 accumulators: 16 packed output pairs.
    unsigned long long acc[16];
    #pragma unroll
    for (int jp = 0; jp < 16; jp++) acc[jp] = pk2(sb0[2 * jp], sb0[2 * jp + 1]);

    // ---- software-pipelined level loop ----
    // Prologue: issue level-0 gathers.
    float fx_c, fy_c;
    unsigned long long g00, g10, g01, g11;
    int r_c;
    {
        const int r = c_res[0];
        const float rf = (float)(r - 1);
        const float fpx = cx * rf, fpy = cy * rf;
        const float fx0 = floorf(fpx), fy0 = floorf(fpy);
        fx_c = fpx - fx0; fy_c = fpy - fy0;
        const int a00 = c_off[0] + (int)fy0 * r + (int)fx0;
        r_c = r;
        g00 = dense[a00];
        g10 = dense[a00 + 1];
        g01 = dense[a00 + r];
        g11 = dense[a00 + r + 1];
    }

    #pragma unroll
    for (int l = 0; l < LL; l++) {
        // Prefetch level l+1 while level l's data is consumed below.
        float fx_n = 0.f, fy_n = 0.f;
        unsigned long long n00 = 0, n10 = 0, n01 = 0, n11 = 0;
        int r_n = 0;
        if (l + 1 < LL) {
            const int r = c_res[l + 1];
            const float rf = (float)(r - 1);
            const float fpx = cx * rf, fpy = cy * rf;
            const float fx0 = floorf(fpx), fy0 = floorf(fpy);
            fx_n = fpx - fx0; fy_n = fpy - fy0;
            const int a00 = c_off[l + 1] + (int)fy0 * r + (int)fx0;
            r_n = r;
            n00 = dense[a00];
            n10 = dense[a00 + 1];
            n01 = dense[a00 + r];
            n11 = dense[a00 + r + 1];
        }

        // Interp level l.
        const float fx = fx_c, fy = fy_c;
        const float w00 = (1.f - fx) * (1.f - fy);
        const float w10 = fx * (1.f - fy);
        const float w01 = (1.f - fx) * fy;
        const float w11 = fx * fy;
        unsigned long long f2 = fma2(g00, pk2(w00, w00), 0ULL);
        f2 = fma2(g10, pk2(w10, w10), f2);
        f2 = fma2(g01, pk2(w01, w01), f2);
        f2 = fma2(g11, pk2(w11, w11), f2);
        float f0, f1; upk2(f2, f0, f1);

        // Rank-2 GEMM update into layer-0 accumulators.
        const unsigned long long f0b = pk2(f0, f0);
        const unsigned long long f1b = pk2(f1, f1);
        const ulonglong2* wr0 = (const ulonglong2*)sW0p[2 * l];
        const ulonglong2* wr1 = (const ulonglong2*)sW0p[2 * l + 1];
        #pragma unroll
        for (int q = 0; q < 8; q++) {
            ulonglong2 wa = wr0[q];
            acc[2 * q]     = fma2(wa.x, f0b, acc[2 * q]);
            acc[2 * q + 1] = fma2(wa.y, f0b, acc[2 * q + 1]);
        }
        #pragma unroll
        for (int q = 0; q < 8; q++) {
            ulonglong2 wb = wr1[q];
            acc[2 * q]     = fma2(wb.x, f1b, acc[2 * q]);
            acc[2 * q + 1] = fma2(wb.y, f1b, acc[2 * q + 1]);
        }

        // Rotate pipeline registers.
        g00 = n00; g10 = n10; g01 = n01; g11 = n11;
        fx_c = fx_n; fy_c = fy_n; r_c = r_n;
    }

    // Layer 1: consume layer-0 accumulators progressively (ReLU in-flight).
    unsigned long long acc1[16];
    #pragma unroll
    for (int jp = 0; jp < 16; jp++) acc1[jp] = pk2(sb1[2 * jp], sb1[2 * jp + 1]);

    #pragma unroll
    for (int ip = 0; ip < 16; ip++) {
        float a, c; upk2(acc[ip], a, c);
        a = fmaxf(a, 0.f); c = fmaxf(c, 0.f);
        const unsigned long long fa = pk2(a, a);
        const unsigned long long fc = pk2(c, c);
        const ulonglong2* wr0 = (const ulonglong2*)sW1p[2 * ip];
        const ulonglong2* wr1 = (const ulonglong2*)sW1p[2 * ip + 1];
        #pragma unroll
        for (int q = 0; q < 8; q++) {
            ulonglong2 wa = wr0[q];
            acc1[2 * q]     = fma2(wa.x, fa, acc1[2 * q]);
            acc1[2 * q + 1] = fma2(wa.y, fa, acc1[2 * q + 1]);
        }
        #pragma unroll
        for (int q = 0; q < 8; q++) {
            ulonglong2 wb = wr1[q];
            acc1[2 * q]     = fma2(wb.x, fc, acc1[2 * q]);
            acc1[2 * q + 1] = fma2(wb.y, fc, acc1[2 * q + 1]);
        }
    }

    // Layer 2: consume layer-1 accumulators progressively, 3 scalar outputs.
    float o0 = sb2[0], o1 = sb2[1], o2 = sb2[2];
    #pragma unroll
    for (int ip = 0; ip < 16; ip++) {
        float a, c; upk2(acc1[ip], a, c);
        a = fmaxf(a, 0.f); c = fmaxf(c, 0.f);
        const int i0 = 2 * ip, i1 = 2 * ip + 1;
        o0 += a * sW2[0][i0] + c * sW2[0][i1];
        o1 += a * sW2[1][i0] + c * sW2[1][i1];
        o2 += a * sW2[2][i0] + c * sW2[2][i1];
    }

    size_t base = (size_t)b * 3 * N_PIX + (size_t)py * RMAX + px;
    out[base]             = tanhf(o0);
    out[base + N_PIX]     = tanhf(o1);
    out[base + 2 * N_PIX] = tanhf(o2);
}

// ---------------------------------------------------------------------------
// Launch
// ---------------------------------------------------------------------------
extern "C" void kernel_launch(void* const* d_in, const int* in_sizes, int n_in,
                              void* d_out, int out_size)
{
    const float* x   = (const float*)d_in[0];
    const float* s   = (const float*)d_in[1];
    const float* w0  = (const float*)d_in[3];
    const float* aw0 = (const float*)d_in[4];
    const float* ab0 = (const float*)d_in[5];
    const float* b0  = (const float*)d_in[6];
    const float* w1  = (const float*)d_in[7];
    const float* aw1 = (const float*)d_in[8];
    const float* ab1 = (const float*)d_in[9];
    const float* b1  = (const float*)d_in[10];
    const float* w2  = (const float*)d_in[11];
    const float* aw2 = (const float*)d_in[12];
    const float* ab2 = (const float*)d_in[13];
    const float* b2  = (const float*)d_in[14];
    float* out = (float*)d_out;

    densify_kernel<<<dim3((NCELLS + 255) / 256, BB), 256>>>(x);
    modweights_kernel<<<BB, 1024>>>(s, w0, aw0, ab0, w1, aw1, ab1, w2, aw2, ab2);
    fused_kernel<<<dim3(256, BB), 256>>>(b0, b1, b2, out);
}

// round 8
// speedup vs baseline: 1.1575x; 1.1575x over previous
#include <cuda_runtime.h>
#include <math.h>

#define BB 8
#define LL 16
#define T_TAB 65536
#define RMAX 256
#define N_PIX (RMAX * RMAX)
#define NCELLS 211538
#define DENS_BLOCKS 827   // ceil(211538 / 256)

__constant__ int c_res[LL] = {16, 19, 23, 28, 34, 40, 49, 58,
                              70, 84, 102, 122, 147, 177, 213, 256};
__constant__ int c_off[LL] = {0, 256, 617, 1146, 1930, 3086, 4686, 7087,
                              10451, 15351, 22407, 32811, 47695, 69304, 100633, 146002};

// Dense (de-hashed) grids.
__device__ float2 g_dense[BB][NCELLS];

// Effective weights. W0p/W1p TRANSPOSED: g_Wp[b][i][j] = Weff[j][i].
__device__ float g_W0p[BB][32][32];
__device__ float g_W1p[BB][32][32];
__device__ float g_W2[BB][3][32];

// ---------------------------------------------------------------------------
// f32x2 helpers
// ---------------------------------------------------------------------------
__device__ __forceinline__ unsigned long long pk2(float lo, float hi) {
    unsigned long long r;
    asm("mov.b64 %0, {%1, %2};" : "=l"(r) : "f"(lo), "f"(hi));
    return r;
}
__device__ __forceinline__ void upk2(unsigned long long v, float& lo, float& hi) {
    asm("mov.b64 {%0, %1}, %2;" : "=f"(lo), "=f"(hi) : "l"(v));
}
__device__ __forceinline__ unsigned long long fma2(unsigned long long a,
                                                   unsigned long long b,
                                                   unsigned long long c) {
    unsigned long long d;
    asm("fma.rn.f32x2 %0, %1, %2, %3;" : "=l"(d) : "l"(a), "l"(b), "l"(c));
    return d;
}

// ---------------------------------------------------------------------------
// Combined prepass: blocks [0, DENS_BLOCKS) de-hash the tables; the one tail
// block per batch computes style projection + modulated weights concurrently.
// Grid: (DENS_BLOCKS + 1, BB), 256 threads.
// ---------------------------------------------------------------------------
__global__ void __launch_bounds__(256)
prepass_kernel(const float* __restrict__ tables,
               const float* __restrict__ s,
               const float* __restrict__ w0, const float* __restrict__ aw0, const float* __restrict__ ab0,
               const float* __restrict__ w1, const float* __restrict__ aw1, const float* __restrict__ ab1,
               const float* __restrict__ w2, const float* __restrict__ aw2, const float* __restrict__ ab2)
{
    const int b = blockIdx.y;
    const int tid = threadIdx.x;

    if (blockIdx.x < DENS_BLOCKS) {
        // ---- densify ----
        const int c = blockIdx.x * 256 + tid;
        if (c >= NCELLS) return;
        int l = 0;
        #pragma unroll
        for (int k = 1; k < LL; k++) l += (c >= c_off[k]);
        const int local = c - c_off[l];
        const int r = c_res[l];
        const int y = local / r;
        const int x = local - y * r;
        const unsigned idx = ((unsigned)x ^ ((unsigned)y * 2654435761u)) & 65535u;
        const float2* tab = (const float2*)tables + ((size_t)b * LL + l) * T_TAB;
        g_dense[b][c] = __ldg(tab + idx);
        return;
    }

    // ---- modweights (one block per batch, 256 threads = 8 warps) ----
    const int wid = tid >> 5, lane = tid & 31;
    __shared__ float st[96];

    const float4* sv4 = (const float4*)(s + b * 512);
    for (int o = wid; o < 96; o += 8) {
        const int layer = o >> 5, i = o & 31;
        const float* aw = (layer == 0) ? aw0 : (layer == 1) ? aw1 : aw2;
        const float* ab = (layer == 0) ? ab0 : (layer == 1) ? ab1 : ab2;
        const float4* rw4 = (const float4*)(aw + i * 512);
        float acc = 0.f;
        #pragma unroll
        for (int it = 0; it < 4; it++) {
            float4 a = __ldg(sv4 + it * 32 + lane);
            float4 w = __ldg(rw4 + it * 32 + lane);
            acc += a.x * w.x + a.y * w.y + a.z * w.z + a.w * w.w;
        }
        #pragma unroll
        for (int d = 16; d > 0; d >>= 1) acc += __shfl_xor_sync(0xFFFFFFFFu, acc, d);
        if (lane == 0) st[o] = acc + __ldg(ab + i);
    }
    __syncthreads();

    if (tid < 32) {
        const int j = tid;
        float wm[32]; float ss = 0.f;
        #pragma unroll
        for (int i = 0; i < 32; i++) { float v = w0[j * 32 + i] * st[i]; wm[i] = v; ss += v * v; }
        float d = rsqrtf(ss + 1e-8f);
        #pragma unroll
        for (int i = 0; i < 32; i++) g_W0p[b][i][j] = wm[i] * d;
    } else if (tid < 64) {
        const int j = tid - 32;
        float wm[32]; float ss = 0.f;
        #pragma unroll
        for (int i = 0; i < 32; i++) { float v = w1[j * 32 + i] * st[32 + i]; wm[i] = v; ss += v * v; }
        float d = rsqrtf(ss + 1e-8f);
        #pragma unroll
        for (int i = 0; i < 32; i++) g_W1p[b][i][j] = wm[i] * d;
    } else if (tid < 67) {
        const int j = tid - 64;
        float wm[32]; float ss = 0.f;
        #pragma unroll
        for (int i = 0; i < 32; i++) { float v = w2[j * 32 + i] * st[64 + i]; wm[i] = v; ss += v * v; }
        float d = rsqrtf(ss + 1e-8f);
        #pragma unroll
        for (int i = 0; i < 32; i++) g_W2[b][j][i] = wm[i] * d;
    }
}

// ---------------------------------------------------------------------------
// Fused: dense bilinear encode + MLP, 2 pixels (x-pair) per thread,
// progressive inter-layer consumption. 32x8 tile / 128 threads.
// launch_bounds(128, 3): cap 170 > demand (~150) => no spill, 3 blocks/SM.
// (Proven R6 configuration — 128-reg caps spill on this kernel.)
// ---------------------------------------------------------------------------
__global__ void __launch_bounds__(128, 3)
fused_kernel(const float* __restrict__ b0, const float* __restrict__ b1,
             const float* __restrict__ b2, float* __restrict__ out)
{
    __shared__ __align__(16) float sW0p[32][32];
    __shared__ __align__(16) float sW1p[32][32];
    __shared__ __align__(16) float sW2[3][32];
    __shared__ float sb0[32], sb1[32], sb2[3];

    const int b = blockIdx.y;
    const int tid = threadIdx.x;

    for (int k = tid; k < 1024; k += 128) {
        ((float*)sW0p)[k] = ((const float*)g_W0p[b])[k];
        ((float*)sW1p)[k] = ((const float*)g_W1p[b])[k];
    }
    if (tid < 96) ((float*)sW2)[tid] = ((const float*)g_W2[b])[tid];
    if (tid < 32) { sb0[tid] = b0[tid]; sb1[tid] = b1[tid]; }
    if (tid < 3)  sb2[tid] = b2[tid];
    __syncthreads();

    // 32x8 tiles: 8 across, 32 down; thread owns an even/odd x-pair.
    const int tile = blockIdx.x;                  // 0..255
    const int px = ((tile & 7) << 5) + ((tid & 15) << 1);
    const int py = ((tile >> 3) << 3) + (tid >> 4);
    const float cxA = (px + 0.5f) * (1.0f / RMAX);
    const float cxB = (px + 1.5f) * (1.0f / RMAX);
    const float cy  = (py + 0.5f) * (1.0f / RMAX);

    const unsigned long long* dense = (const unsigned long long*)g_dense[b];

    unsigned long long accA[16], accB[16];
    #pragma unroll
    for (int jp = 0; jp < 16; jp++) {
        unsigned long long bb = pk2(sb0[2 * jp], sb0[2 * jp + 1]);
        accA[jp] = bb; accB[jp] = bb;
    }

    #pragma unroll
    for (int l = 0; l < LL; l++) {
        const int r = c_res[l];
        const float rf = (float)(r - 1);
        const float fpy = cy * rf;
        const float fy0 = floorf(fpy);
        const float fy = fpy - fy0;
        const int rowbase = c_off[l] + (int)fy0 * r;

        float fA0, fA1, fB0, fB1;
        {
            const float fpx = cxA * rf;
            const float fx0f = floorf(fpx);
            const float fx = fpx - fx0f;
            const int a00 = rowbase + (int)fx0f;
            const unsigned long long g00 = dense[a00];
            const unsigned long long g10 = dense[a00 + 1];
            const unsigned long long g01 = dense[a00 + r];
            const unsigned long long g11 = dense[a00 + r + 1];
            const float w00 = (1.f - fx) * (1.f - fy);
            const float w10 = fx * (1.f - fy);
            const float w01 = (1.f - fx) * fy;
            const float w11 = fx * fy;
            unsigned long long f2 = fma2(g00, pk2(w00, w00), 0ULL);
            f2 = fma2(g10, pk2(w10, w10), f2);
            f2 = fma2(g01, pk2(w01, w01), f2);
            f2 = fma2(g11, pk2(w11, w11), f2);
            upk2(f2, fA0, fA1);
        }
        {
            const float fpx = cxB * rf;
            const float fx0f = floorf(fpx);
            const float fx = fpx - fx0f;
            const int a00 = rowbase + (int)fx0f;
            const unsigned long long g00 = dense[a00];
            const unsigned long long g10 = dense[a00 + 1];
            const unsigned long long g01 = dense[a00 + r];
            const unsigned long long g11 = dense[a00 + r + 1];
            const float w00 = (1.f - fx) * (1.f - fy);
            const float w10 = fx * (1.f - fy);
            const float w01 = (1.f - fx) * fy;
            const float w11 = fx * fy;
            unsigned long long f2 = fma2(g00, pk2(w00, w00), 0ULL);
            f2 = fma2(g10, pk2(w10, w10), f2);
            f2 = fma2(g01, pk2(w01, w01), f2);
            f2 = fma2(g11, pk2(w11, w11), f2);
            upk2(f2, fB0, fB1);
        }

        const unsigned long long fA0b = pk2(fA0, fA0), fA1b = pk2(fA1, fA1);
        const unsigned long long fB0b = pk2(fB0, fB0), fB1b = pk2(fB1, fB1);
        const ulonglong2* wr0 = (const ulonglong2*)sW0p[2 * l];
        const ulonglong2* wr1 = (const ulonglong2*)sW0p[2 * l + 1];
        #pragma unroll
        for (int q = 0; q < 8; q++) {
            ulonglong2 wa = wr0[q];
            accA[2 * q]     = fma2(wa.x, fA0b, accA[2 * q]);
            accA[2 * q + 1] = fma2(wa.y, fA0b, accA[2 * q + 1]);
            accB[2 * q]     = fma2(wa.x, fB0b, accB[2 * q]);
            accB[2 * q + 1] = fma2(wa.y, fB0b, accB[2 * q + 1]);
        }
        #pragma unroll
        for (int q = 0; q < 8; q++) {
            ulonglong2 wb = wr1[q];
            accA[2 * q]     = fma2(wb.x, fA1b, accA[2 * q]);
            accA[2 * q + 1] = fma2(wb.y, fA1b, accA[2 * q + 1]);
            accB[2 * q]     = fma2(wb.x, fB1b, accB[2 * q]);
            accB[2 * q + 1] = fma2(wb.y, fB1b, accB[2 * q + 1]);
        }
    }

    // Layer 1: consume layer-0 accumulators progressively (ReLU in-flight).
    unsigned long long acc1A[16], acc1B[16];
    #pragma unroll
    for (int jp = 0; jp < 16; jp++) {
        unsigned long long bb = pk2(sb1[2 * jp], sb1[2 * jp + 1]);
        acc1A[jp] = bb; acc1B[jp] = bb;
    }
    #pragma unroll
    for (int ip = 0; ip < 16; ip++) {
        float a0, a1, b0v, b1v;
        upk2(accA[ip], a0, a1);
        upk2(accB[ip], b0v, b1v);
        a0 = fmaxf(a0, 0.f); a1 = fmaxf(a1, 0.f);
        b0v = fmaxf(b0v, 0.f); b1v = fmaxf(b1v, 0.f);
        const unsigned long long fa0 = pk2(a0, a0), fa1 = pk2(a1, a1);
        const unsigned long long fb0 = pk2(b0v, b0v), fb1 = pk2(b1v, b1v);
        const ulonglong2* wr0 = (const ulonglong2*)sW1p[2 * ip];
        const ulonglong2* wr1 = (const ulonglong2*)sW1p[2 * ip + 1];
        #pragma unroll
        for (int q = 0; q < 8; q++) {
            ulonglong2 wa = wr0[q];
            acc1A[2 * q]     = fma2(wa.x, fa0, acc1A[2 * q]);
            acc1A[2 * q + 1] = fma2(wa.y, fa0, acc1A[2 * q + 1]);
            acc1B[2 * q]     = fma2(wa.x, fb0, acc1B[2 * q]);
            acc1B[2 * q + 1] = fma2(wa.y, fb0, acc1B[2 * q + 1]);
        }
        #pragma unroll
        for (int q = 0; q < 8; q++) {
            ulonglong2 wb = wr1[q];
            acc1A[2 * q]     = fma2(wb.x, fa1, acc1A[2 * q]);
            acc1A[2 * q + 1] = fma2(wb.y, fa1, acc1A[2 * q + 1]);
            acc1B[2 * q]     = fma2(wb.x, fb1, acc1B[2 * q]);
            acc1B[2 * q + 1] = fma2(wb.y, fb1, acc1B[2 * q + 1]);
        }
    }

    // Layer 2: consume layer-1 accumulators progressively.
    // f32x2 lanes hold (pixelA, pixelB) for each of 3 outputs.
    unsigned long long o0 = pk2(sb2[0], sb2[0]);
    unsigned long long o1 = pk2(sb2[1], sb2[1]);
    unsigned long long o2 = pk2(sb2[2], sb2[2]);
    #pragma unroll
    for (int ip = 0; ip < 16; ip++) {
        float a0, a1, b0v, b1v;
        upk2(acc1A[ip], a0, a1);
        upk2(acc1B[ip], b0v, b1v);
        a0 = fmaxf(a0, 0.f); a1 = fmaxf(a1, 0.f);
        b0v = fmaxf(b0v, 0.f); b1v = fmaxf(b1v, 0.f);
        const unsigned long long h_i0 = pk2(a0, b0v);
        const unsigned long long h_i1 = pk2(a1, b1v);
        const int i0 = 2 * ip, i1 = 2 * ip + 1;
        o0 = fma2(h_i0, pk2(sW2[0][i0], sW2[0][i0]), o0);
        o0 = fma2(h_i1, pk2(sW2[0][i1], sW2[0][i1]), o0);
        o1 = fma2(h_i0, pk2(sW2[1][i0], sW2[1][i0]), o1);
        o1 = fma2(h_i1, pk2(sW2[1][i1], sW2[1][i1]), o1);
        o2 = fma2(h_i0, pk2(sW2[2][i0], sW2[2][i0]), o2);
        o2 = fma2(h_i1, pk2(sW2[2][i1], sW2[2][i1]), o2);
    }

    float oA0, oB0, oA1, oB1, oA2, oB2;
    upk2(o0, oA0, oB0);
    upk2(o1, oA1, oB1);
    upk2(o2, oA2, oB2);

    size_t base = (size_t)b * 3 * N_PIX + (size_t)py * RMAX + px;
    *(float2*)(out + base)             = make_float2(tanhf(oA0), tanhf(oB0));
    *(float2*)(out + base + N_PIX)     = make_float2(tanhf(oA1), tanhf(oB1));
    *(float2*)(out + base + 2 * N_PIX) = make_float2(tanhf(oA2), tanhf(oB2));
}

// ---------------------------------------------------------------------------
// Launch
// ---------------------------------------------------------------------------
extern "C" void kernel_launch(void* const* d_in, const int* in_sizes, int n_in,
                              void* d_out, int out_size)
{
    const float* x   = (const float*)d_in[0];
    const float* s   = (const float*)d_in[1];
    const float* w0  = (const float*)d_in[3];
    const float* aw0 = (const float*)d_in[4];
    const float* ab0 = (const float*)d_in[5];
    const float* b0  = (const float*)d_in[6];
    const float* w1  = (const float*)d_in[7];
    const float* aw1 = (const float*)d_in[8];
    const float* ab1 = (const float*)d_in[9];
    const float* b1  = (const float*)d_in[10];
    const float* w2  = (const float*)d_in[11];
    const float* aw2 = (const float*)d_in[12];
    const float* ab2 = (const float*)d_in[13];
    const float* b2  = (const float*)d_in[14];
    float* out = (float*)d_out;

    prepass_kernel<<<dim3(DENS_BLOCKS + 1, BB), 256>>>(
        x, s, w0, aw0, ab0, w1, aw1, ab1, w2, aw2, ab2);
    fused_kernel<<<dim3(256, BB), 128>>>(b0, b1, b2, out);
}

// round 10
// speedup vs baseline: 1.3811x; 1.1931x over previous
#include <cuda_runtime.h>
#include <cuda_bf16.h>
#include <math.h>
#include <cstdint>

#define BB 8
#define LL 16
#define T_TAB 65536
#define RMAX 256
#define N_PIX (RMAX * RMAX)
#define NCELLS 211538

#define WPITCH 40   // bf16 elements per row (80B) -> conflict-free frag loads

__constant__ int c_res[LL] = {16, 19, 23, 28, 34, 40, 49, 58,
                              70, 84, 102, 122, 147, 177, 213, 256};
__constant__ int c_off[LL] = {0, 256, 617, 1146, 1930, 3086, 4686, 7087,
                              10451, 15351, 22407, 32811, 47695, 69304, 100633, 146002};

// Dense (de-hashed) grids.
__device__ float2 g_dense[BB][NCELLS];

// Effective weights, ROW-MAJOR [out][in] (= mma B operand [n][k]).
__device__ float g_W0[BB][32][32];
__device__ float g_W1[BB][32][32];
__device__ float g_W2[BB][3][32];

// ---------------------------------------------------------------------------
// Warp-level bf16 MMA (baseline PTX, no sm_103a-only features)
// ---------------------------------------------------------------------------
__device__ __forceinline__ void mma16816(float* c,
                                         uint32_t a0, uint32_t a1, uint32_t a2, uint32_t a3,
                                         uint32_t b0, uint32_t b1) {
    asm volatile("mma.sync.aligned.m16n8k16.row.col.f32.bf16.bf16.f32 "
                 "{%0,%1,%2,%3}, {%4,%5,%6,%7}, {%8,%9}, {%0,%1,%2,%3};"
                 : "+f"(c[0]), "+f"(c[1]), "+f"(c[2]), "+f"(c[3])
                 : "r"(a0), "r"(a1), "r"(a2), "r"(a3), "r"(b0), "r"(b1));
}

__device__ __forceinline__ uint32_t pack_bf16(float lo, float hi) {
    __nv_bfloat16 l = __float2bfloat16_rn(lo);
    __nv_bfloat16 h = __float2bfloat16_rn(hi);
    return ((uint32_t)__bfloat16_as_ushort(h) << 16) | (uint32_t)__bfloat16_as_ushort(l);
}

// ---------------------------------------------------------------------------
// Style projection + weight modulation, one block per batch (1024 threads).
// ---------------------------------------------------------------------------
__global__ void __launch_bounds__(1024)
modweights_kernel(const float* __restrict__ s,
                  const float* __restrict__ w0, const float* __restrict__ aw0, const float* __restrict__ ab0,
                  const float* __restrict__ w1, const float* __restrict__ aw1, const float* __restrict__ ab1,
                  const float* __restrict__ w2, const float* __restrict__ aw2, const float* __restrict__ ab2)
{
    const int b = blockIdx.x;
    const int wid = threadIdx.x >> 5, lane = threadIdx.x & 31;
    __shared__ float st[96];

    const float4* sv4 = (const float4*)(s + b * 512);
    for (int o = wid; o < 96; o += 32) {
        const int layer = o >> 5, i = o & 31;
        const float* aw = (layer == 0) ? aw0 : (layer == 1) ? aw1 : aw2;
        const float* ab = (layer == 0) ? ab0 : (layer == 1) ? ab1 : ab2;
        const float4* rw4 = (const float4*)(aw + i * 512);
        float acc = 0.f;
        #pragma unroll
        for (int it = 0; it < 4; it++) {
            float4 a = __ldg(sv4 + it * 32 + lane);
            float4 w = __ldg(rw4 + it * 32 + lane);
            acc += a.x * w.x + a.y * w.y + a.z * w.z + a.w * w.w;
        }
        #pragma unroll
        for (int d = 16; d > 0; d >>= 1) acc += __shfl_xor_sync(0xFFFFFFFFu, acc, d);
        if (lane == 0) st[o] = acc + __ldg(ab + i);
    }
    __syncthreads();

    const int tid = threadIdx.x;
    if (tid < 32) {
        const int j = tid;
        float wm[32]; float ss = 0.f;
        #pragma unroll
        for (int i = 0; i < 32; i++) { float v = w0[j * 32 + i] * st[i]; wm[i] = v; ss += v * v; }
        float d = rsqrtf(ss + 1e-8f);
        #pragma unroll
        for (int i = 0; i < 32; i++) g_W0[b][j][i] = wm[i] * d;
    } else if (tid < 64) {
        const int j = tid - 32;
        float wm[32]; float ss = 0.f;
        #pragma unroll
        for (int i = 0; i < 32; i++) { float v = w1[j * 32 + i] * st[32 + i]; wm[i] = v; ss += v * v; }
        float d = rsqrtf(ss + 1e-8f);
        #pragma unroll
        for (int i = 0; i < 32; i++) g_W1[b][j][i] = wm[i] * d;
    } else if (tid < 67) {
        const int j = tid - 64;
        float wm[32]; float ss = 0.f;
        #pragma unroll
        for (int i = 0; i < 32; i++) { float v = w2[j * 32 + i] * st[64 + i]; wm[i] = v; ss += v * v; }
        float d = rsqrtf(ss + 1e-8f);
        #pragma unroll
        for (int i = 0; i < 32; i++) g_W2[b][j][i] = wm[i] * d;
    }
}

// ---------------------------------------------------------------------------
// De-hash tables into dense per-level grids.
// ---------------------------------------------------------------------------
__global__ void __launch_bounds__(256)
densify_kernel(const float* __restrict__ tables)
{
    const int c = blockIdx.x * 256 + threadIdx.x;
    const int b = blockIdx.y;
    if (c >= NCELLS) return;
    int l = 0;
    #pragma unroll
    for (int k = 1; k < LL; k++) l += (c >= c_off[k]);
    const int local = c - c_off[l];
    const int r = c_res[l];
    const int y = local / r;
    const int x = local - y * r;
    const unsigned idx = ((unsigned)x ^ ((unsigned)y * 2654435761u)) & 65535u;
    const float2* tab = (const float2*)tables + ((size_t)b * LL + l) * T_TAB;
    g_dense[b][c] = __ldg(tab + idx);
}

// ---------------------------------------------------------------------------
// One MMA layer: C[2][4][4] += sum over 3 split passes of A(32x32) * B(32x32)^T
// A rows = pixels (feature buffers), B rows = weight outputs [n][k].
// ---------------------------------------------------------------------------
__device__ __forceinline__ void mma_layer(
    float C[2][4][4],
    const __nv_bfloat16 (*Fh)[WPITCH], const __nv_bfloat16 (*Fl)[WPITCH],
    const __nv_bfloat16 (*Wh)[WPITCH], const __nv_bfloat16 (*Wl)[WPITCH],
    int g, int tg)
{
    #pragma unroll
    for (int pass = 0; pass < 3; pass++) {
        const __nv_bfloat16 (*A)[WPITCH] = (pass == 2) ? Fl : Fh;
        const __nv_bfloat16 (*B)[WPITCH] = (pass == 1) ? Wl : Wh;
        #pragma unroll
        for (int kt = 0; kt < 2; kt++) {
            const int kc = kt * 16 + 2 * tg;
            uint32_t a[2][4];
            #pragma unroll
            for (int mt = 0; mt < 2; mt++) {
                a[mt][0] = *(const uint32_t*)&A[mt * 16 + g][kc];
                a[mt][1] = *(const uint32_t*)&A[mt * 16 + g + 8][kc];
                a[mt][2] = *(const uint32_t*)&A[mt * 16 + g][kc + 8];
                a[mt][3] = *(const uint32_t*)&A[mt * 16 + g + 8][kc + 8];
            }
            #pragma unroll
            for (int nt = 0; nt < 4; nt++) {
                const uint32_t b0 = *(const uint32_t*)&B[nt * 8 + g][kc];
                const uint32_t b1 = *(const uint32_t*)&B[nt * 8 + g][kc + 8];
                #pragma unroll
                for (int mt = 0; mt < 2; mt++)
                    mma16816(C[mt][nt], a[mt][0], a[mt][1], a[mt][2], a[mt][3], b0, b1);
            }
        }
    }
}

// ---------------------------------------------------------------------------
// Fused kernel: encode (fp32) + MLP layers 0/1 on HMMA (bf16 hi+lo split)
// + layer 2 fp32. Block = 128 threads = 4 warps; warp = 32 consecutive
// x-pixels (M=32 rows). Grid (512, BB).
// ---------------------------------------------------------------------------
__global__ void __launch_bounds__(128)
fused_kernel(const float* __restrict__ b0, const float* __restrict__ b1,
             const float* __restrict__ b2, float* __restrict__ out)
{
    __shared__ __nv_bfloat16 sW0h[32][WPITCH], sW0l[32][WPITCH];
    __shared__ __nv_bfloat16 sW1h[32][WPITCH], sW1l[32][WPITCH];
    __shared__ __nv_bfloat16 sFh[4][32][WPITCH], sFl[4][32][WPITCH];
    __shared__ float sB0[32], sB1[32], sB2[3], sW2[3][32];

    const int b = blockIdx.y;
    const int tid = threadIdx.x;
    const int wid = tid >> 5;
    const int lane = tid & 31;
    const int g = lane >> 2;     // group id 0..7
    const int tg = lane & 3;     // thread-in-group 0..3

    // Stage effective weights (hi/lo bf16 split) + biases + W2.
    for (int e = tid; e < 1024; e += 128) {
        const int j = e >> 5, i = e & 31;
        float w = g_W0[b][j][i];
        __nv_bfloat16 hi = __float2bfloat16_rn(w);
        sW0h[j][i] = hi;
        sW0l[j][i] = __float2bfloat16_rn(w - __bfloat162float(hi));
        w = g_W1[b][j][i];
        hi = __float2bfloat16_rn(w);
        sW1h[j][i] = hi;
        sW1l[j][i] = __float2bfloat16_rn(w - __bfloat162float(hi));
    }
    if (tid < 32) { sB0[tid] = b0[tid]; sB1[tid] = b1[tid]; }
    if (tid < 3)  sB2[tid] = b2[tid];
    if (tid < 96) ((float*)sW2)[tid] = ((const float*)g_W2[b])[tid];
    __syncthreads();

    // Pixel mapping: warp covers 32 consecutive x; block covers 32x4 tile.
    const int pxbase = (blockIdx.x & 7) * 32;
    const int py = (blockIdx.x >> 3) * 4 + wid;
    const int px = pxbase + lane;
    const float cx = (px + 0.5f) * (1.0f / RMAX);
    const float cy = (py + 0.5f) * (1.0f / RMAX);

    const float2* dense = (const float2*)g_dense[b];

    // ---- encode: 16 levels -> 32 fp32 features ----
    float feat[32];
    #pragma unroll
    for (int l = 0; l < LL; l++) {
        const int r = c_res[l];
        const float rf = (float)(r - 1);
        const float fpx = cx * rf, fpy = cy * rf;
        const float fx0 = floorf(fpx), fy0 = floorf(fpy);
        const float fx = fpx - fx0, fy = fpy - fy0;
        const int a00 = c_off[l] + (int)fy0 * r + (int)fx0;
        const float2 q00 = __ldg(dense + a00);
        const float2 q10 = __ldg(dense + a00 + 1);
        const float2 q01 = __ldg(dense + a00 + r);
        const float2 q11 = __ldg(dense + a00 + r + 1);
        const float w00 = (1.f - fx) * (1.f - fy);
        const float w10 = fx * (1.f - fy);
        const float w01 = (1.f - fx) * fy;
        const float w11 = fx * fy;
        feat[2 * l]     = q00.x * w00 + q10.x * w10 + q01.x * w01 + q11.x * w11;
        feat[2 * l + 1] = q00.y * w00 + q10.y * w10 + q01.y * w01 + q11.y * w11;
    }

    // ---- split features -> per-warp SMEM (row = lane = pixel) ----
    #pragma unroll
    for (int c = 0; c < 16; c++) {
        const float f0 = feat[2 * c], f1 = feat[2 * c + 1];
        const float h0 = __bfloat162float(__float2bfloat16_rn(f0));
        const float h1 = __bfloat162float(__float2bfloat16_rn(f1));
        *(uint32_t*)&sFh[wid][lane][2 * c] = pack_bf16(f0, f1);
        *(uint32_t*)&sFl[wid][lane][2 * c] = pack_bf16(f0 - h0, f1 - h1);
    }
    __syncwarp();

    // ---- layer 0 on tensor pipe ----
    float C[2][4][4];
    #pragma unroll
    for (int mt = 0; mt < 2; mt++)
        #pragma unroll
        for (int nt = 0; nt < 4; nt++)
            #pragma unroll
            for (int k = 0; k < 4; k++) C[mt][nt][k] = 0.f;
    mma_layer(C, sFh[wid], sFl[wid], sW0h, sW0l, g, tg);
    __syncwarp();   // done reading features; buffers about to be overwritten

    // ---- epilogue 0: bias + ReLU, re-split into feature buffers ----
    #pragma unroll
    for (int mt = 0; mt < 2; mt++) {
        #pragma unroll
        for (int nt = 0; nt < 4; nt++) {
            const int col = nt * 8 + 2 * tg;
            const float h00 = fmaxf(C[mt][nt][0] + sB0[col], 0.f);
            const float h01 = fmaxf(C[mt][nt][1] + sB0[col + 1], 0.f);
            const float h10 = fmaxf(C[mt][nt][2] + sB0[col], 0.f);
            const float h11 = fmaxf(C[mt][nt][3] + sB0[col + 1], 0.f);
            const int r0 = mt * 16 + g, r1 = mt * 16 + g + 8;
            *(uint32_t*)&sFh[wid][r0][col] = pack_bf16(h00, h01);
            *(uint32_t*)&sFh[wid][r1][col] = pack_bf16(h10, h11);
            const float t00 = __bfloat162float(__float2bfloat16_rn(h00));
            const float t01 = __bfloat162float(__float2bfloat16_rn(h01));
            const float t10 = __bfloat162float(__float2bfloat16_rn(h10));
            const float t11 = __bfloat162float(__float2bfloat16_rn(h11));
            *(uint32_t*)&sFl[wid][r0][col] = pack_bf16(h00 - t00, h01 - t01);
            *(uint32_t*)&sFl[wid][r1][col] = pack_bf16(h10 - t10, h11 - t11);
        }
    }
    __syncwarp();

    // ---- layer 1 on tensor pipe ----
    #pragma unroll
    for (int mt = 0; mt < 2; mt++)
        #pragma unroll
        for (int nt = 0; nt < 4; nt++)
            #pragma unroll
            for (int k = 0; k < 4; k++) C[mt][nt][k] = 0.f;
    mma_layer(C, sFh[wid], sFl[wid], sW1h, sW1l, g, tg);

    // ---- epilogue 1 + layer 2 (fp32) + tanh + output ----
    float po[3][4];
    #pragma unroll
    for (int cc = 0; cc < 3; cc++)
        #pragma unroll
        for (int k = 0; k < 4; k++) po[cc][k] = 0.f;

    #pragma unroll
    for (int mt = 0; mt < 2; mt++) {
        #pragma unroll
        for (int nt = 0; nt < 4; nt++) {
            const int col = nt * 8 + 2 * tg;
            const float h00 = fmaxf(C[mt][nt][0] + sB1[col], 0.f);
            const float h01 = fmaxf(C[mt][nt][1] + sB1[col + 1], 0.f);
            const float h10 = fmaxf(C[mt][nt][2] + sB1[col], 0.f);
            const float h11 = fmaxf(C[mt][nt][3] + sB1[col + 1], 0.f);
            #pragma unroll
            for (int cc = 0; cc < 3; cc++) {
                const float wv0 = sW2[cc][col];
                const float wv1 = sW2[cc][col + 1];
                po[cc][mt * 2]     += h00 * wv0 + h01 * wv1;
                po[cc][mt * 2 + 1] += h10 * wv0 + h11 * wv1;
            }
        }
    }
    // reduce over tg (4 lanes per group)
    #pragma unroll
    for (int cc = 0; cc < 3; cc++)
        #pragma unroll
        for (int k = 0; k < 4; k++) {
            po[cc][k] += __shfl_xor_sync(0xFFFFFFFFu, po[cc][k], 1);
            po[cc][k] += __shfl_xor_sync(0xFFFFFFFFu, po[cc][k], 2);
        }

    if (tg == 0) {
        #pragma unroll
        for (int mt = 0; mt < 2; mt++) {
            #pragma unroll
            for (int rh = 0; rh < 2; rh++) {
                const int row = mt * 16 + g + rh * 8;     // pixel row in warp tile
                const size_t base = (size_t)b * 3 * N_PIX + (size_t)py * RMAX + (pxbase + row);
                #pragma unroll
                for (int cc = 0; cc < 3; cc++)
                    out[base + (size_t)cc * N_PIX] = tanhf(sB2[cc] + po[cc][mt * 2 + rh]);
            }
        }
    }
}

// ---------------------------------------------------------------------------
// Launch
// ---------------------------------------------------------------------------
extern "C" void kernel_launch(void* const* d_in, const int* in_sizes, int n_in,
                              void* d_out, int out_size)
{
    const float* x   = (const float*)d_in[0];
    const float* s   = (const float*)d_in[1];
    const float* w0  = (const float*)d_in[3];
    const float* aw0 = (const float*)d_in[4];
    const float* ab0 = (const float*)d_in[5];
    const float* b0  = (const float*)d_in[6];
    const float* w1  = (const float*)d_in[7];
    const float* aw1 = (const float*)d_in[8];
    const float* ab1 = (const float*)d_in[9];
    const float* b1  = (const float*)d_in[10];
    const float* w2  = (const float*)d_in[11];
    const float* aw2 = (const float*)d_in[12];
    const float* ab2 = (const float*)d_in[13];
    const float* b2  = (const float*)d_in[14];
    float* out = (float*)d_out;

    densify_kernel<<<dim3((NCELLS + 255) / 256, BB), 256>>>(x);
    modweights_kernel<<<BB, 1024>>>(s, w0, aw0, ab0, w1, aw1, ab1, w2, aw2, ab2);
    fused_kernel<<<dim3(512, BB), 128>>>(b0, b1, b2, out);
}